// round 1
// baseline (speedup 1.0000x reference)
#include <cuda_runtime.h>
#include <math.h>

#define NTOK 8192
#define DDIM 1024
#define HDIM 512
#define EEXP 6
#define FDIM 1536
#define LN_EPS 1e-5f

// ---------------- scratch (device globals; allocation-free rule) ----------------
__device__ float g_h[(size_t)NTOK * HDIM];                 // router hidden (reused post-LN)
__device__ int   g_counts[EEXP];
__device__ int   g_lists[(size_t)EEXP * NTOK];             // token ids per expert
__device__ int   g_as_e[NTOK * 2];                         // per-token: expert ids (top2)
__device__ int   g_as_s[NTOK * 2];                         // per-token: slot in expert list
__device__ float g_as_w[NTOK * 2];                         // per-token: gate weights
__device__ float g_act[(size_t)EEXP * NTOK * FDIM];        // expert mid activations
__device__ float g_y[(size_t)EEXP * NTOK * DDIM];          // expert outputs (pre-gate)

// ---------------- helpers ----------------
__device__ __forceinline__ float gelu_exact(float x) {
    return 0.5f * x * (1.0f + erff(x * 0.70710678118654752440f));
}
__device__ __forceinline__ float silu(float x) {
    return x / (1.0f + expf(-x));
}

// ---------------- reset ----------------
__global__ void reset_kernel() {
    if (threadIdx.x < EEXP) g_counts[threadIdx.x] = 0;
}

// ---------------- generic tiled GEMM ----------------
// C[e][m][n] = act( A_e[row(m)][:] . B[e][:][n] + bias[e][n] )
//   A_e = A + e*a_estride ; row(m) = lists ? lists[e*Mfull+m] : m
//   M per expert = counts ? counts[e] : Mfull
// Tiles: BM=128, BN=64, BK=16; 256 threads; 8x4 per-thread microtile.
#define BM 128
#define BN 64
#define BK 16
#define TM 8
#define TN 4

__global__ __launch_bounds__(256) void gemm_kernel(
    const float* __restrict__ A, const float* __restrict__ Bmat,
    const float* __restrict__ bias, float* __restrict__ C,
    const int* __restrict__ lists, const int* __restrict__ counts,
    int Mfull, int K, int Nn, int lda, size_t a_estride, int act_sel)
{
    const int e = blockIdx.y;
    const int Mcur = counts ? counts[e] : Mfull;
    const int m0 = blockIdx.x * BM;
    if (m0 >= Mcur) return;
    const int n0 = blockIdx.z * BN;

    const float* Ap    = A + (size_t)e * a_estride;
    const float* Bp    = Bmat + (size_t)e * K * Nn;
    const float* biasp = bias + (size_t)e * Nn;
    float*       Cp    = C + (size_t)e * (size_t)Mfull * Nn;
    const int*   list  = lists ? (lists + (size_t)e * Mfull) : nullptr;

    __shared__ float As[BK][BM + 4];
    __shared__ float Bs[BK][BN];

    const int tid = threadIdx.x;
    const int tx = tid & 15;   // n dir (4 cols each)
    const int ty = tid >> 4;   // m dir (8 rows each)

    // A-load mapping: two rows per thread
    const int arow = tid >> 2;           // 0..63
    const int ak4  = (tid & 3) * 4;      // 0,4,8,12
    const int gr0 = m0 + arow;
    const int gr1 = m0 + arow + 64;
    const bool v0 = gr0 < Mcur;
    const bool v1 = gr1 < Mcur;
    int sr0 = v0 ? (list ? list[gr0] : gr0) : 0;
    int sr1 = v1 ? (list ? list[gr1] : gr1) : 0;
    const float* Arow0 = Ap + (size_t)sr0 * lda;
    const float* Arow1 = Ap + (size_t)sr1 * lda;

    // B-load mapping: one float4 per thread
    const int bk  = tid >> 4;            // 0..15
    const int bn4 = (tid & 15) * 4;      // 0..60

    float acc[TM][TN];
#pragma unroll
    for (int i = 0; i < TM; i++)
#pragma unroll
        for (int j = 0; j < TN; j++) acc[i][j] = 0.0f;

    for (int k0 = 0; k0 < K; k0 += BK) {
        float4 a0 = make_float4(0.f, 0.f, 0.f, 0.f);
        float4 a1 = make_float4(0.f, 0.f, 0.f, 0.f);
        if (v0) a0 = *(const float4*)(Arow0 + k0 + ak4);
        if (v1) a1 = *(const float4*)(Arow1 + k0 + ak4);
        As[ak4 + 0][arow] = a0.x; As[ak4 + 1][arow] = a0.y;
        As[ak4 + 2][arow] = a0.z; As[ak4 + 3][arow] = a0.w;
        As[ak4 + 0][arow + 64] = a1.x; As[ak4 + 1][arow + 64] = a1.y;
        As[ak4 + 2][arow + 64] = a1.z; As[ak4 + 3][arow + 64] = a1.w;

        float4 b = *(const float4*)(Bp + (size_t)(k0 + bk) * Nn + n0 + bn4);
        *(float4*)&Bs[bk][bn4] = b;
        __syncthreads();

#pragma unroll
        for (int k = 0; k < BK; k++) {
            float4 a01 = *(const float4*)&As[k][ty * TM];
            float4 a23 = *(const float4*)&As[k][ty * TM + 4];
            float4 bv  = *(const float4*)&Bs[k][tx * TN];
            float av[TM] = {a01.x, a01.y, a01.z, a01.w, a23.x, a23.y, a23.z, a23.w};
            float bb[TN] = {bv.x, bv.y, bv.z, bv.w};
#pragma unroll
            for (int i = 0; i < TM; i++)
#pragma unroll
                for (int j = 0; j < TN; j++)
                    acc[i][j] = fmaf(av[i], bb[j], acc[i][j]);
        }
        __syncthreads();
    }

    // epilogue
    const bool even_e = ((e & 1) == 0);
#pragma unroll
    for (int i = 0; i < TM; i++) {
        int m = m0 + ty * TM + i;
        if (m >= Mcur) continue;
#pragma unroll
        for (int j = 0; j < TN; j++) {
            int n = n0 + tx * TN + j;
            float v = acc[i][j] + biasp[n];
            if (act_sel == 1) v = even_e ? gelu_exact(v) : silu(v);
            Cp[(size_t)m * Nn + n] = v;
        }
    }
}

// ---------------- LayerNorm + exact GELU on g_h rows (H=512) ----------------
__global__ __launch_bounds__(256) void ln_gelu_kernel(
    const float* __restrict__ ln_g, const float* __restrict__ ln_b)
{
    const int n = blockIdx.x;
    float* row = g_h + (size_t)n * HDIM;
    const int t = threadIdx.x;
    __shared__ float red[256];

    float v0 = row[t];
    float v1 = row[t + 256];
    red[t] = v0 + v1;
    __syncthreads();
    for (int s = 128; s > 0; s >>= 1) {
        if (t < s) red[t] += red[t + s];
        __syncthreads();
    }
    float mean = red[0] * (1.0f / HDIM);
    __syncthreads();

    float d0 = v0 - mean, d1 = v1 - mean;
    red[t] = d0 * d0 + d1 * d1;
    __syncthreads();
    for (int s = 128; s > 0; s >>= 1) {
        if (t < s) red[t] += red[t + s];
        __syncthreads();
    }
    float var = red[0] * (1.0f / HDIM);
    float inv = rsqrtf(var + LN_EPS);

    float o0 = d0 * inv * ln_g[t] + ln_b[t];
    float o1 = d1 * inv * ln_g[t + 256] + ln_b[t + 256];
    row[t]       = gelu_exact(o0);
    row[t + 256] = gelu_exact(o1);
}

// ---------------- router stage 2: logits -> softmax -> top2 -> lists ----------------
__global__ __launch_bounds__(128) void router2_kernel(
    const float* __restrict__ r2w, const float* __restrict__ r2b,
    const float* __restrict__ temp, const float* __restrict__ rbias)
{
    const int n = blockIdx.x;
    const int t = threadIdx.x;  // 128 threads
    const float* row = g_h + (size_t)n * HDIM;

    float acc[EEXP];
#pragma unroll
    for (int e = 0; e < EEXP; e++) acc[e] = 0.0f;

    for (int k = t; k < HDIM; k += 128) {
        float hv = row[k];
#pragma unroll
        for (int e = 0; e < EEXP; e++)
            acc[e] = fmaf(hv, r2w[k * EEXP + e], acc[e]);
    }

    __shared__ float red[EEXP][128];
#pragma unroll
    for (int e = 0; e < EEXP; e++) red[e][t] = acc[e];
    __syncthreads();

    __shared__ float logits[EEXP];
    if (t < EEXP) {
        float s = 0.0f;
        for (int i = 0; i < 128; i++) s += red[t][i];
        logits[t] = (s + r2b[t]) / temp[0] + rbias[t];
    }
    __syncthreads();

    if (t == 0) {
        float mx = logits[0];
#pragma unroll
        for (int e = 1; e < EEXP; e++) mx = fmaxf(mx, logits[e]);
        float p[EEXP];
        float den = 0.0f;
#pragma unroll
        for (int e = 0; e < EEXP; e++) { p[e] = expf(logits[e] - mx); den += p[e]; }
        float inv = 1.0f / den;
#pragma unroll
        for (int e = 0; e < EEXP; e++) p[e] *= inv;

        int i0 = 0; float v0 = p[0];
#pragma unroll
        for (int e = 1; e < EEXP; e++) if (p[e] > v0) { v0 = p[e]; i0 = e; }
        int i1 = -1; float v1 = -1.0f;
#pragma unroll
        for (int e = 0; e < EEXP; e++) if (e != i0 && p[e] > v1) { v1 = p[e]; i1 = e; }

        int s0 = atomicAdd(&g_counts[i0], 1);
        int s1 = atomicAdd(&g_counts[i1], 1);
        g_lists[(size_t)i0 * NTOK + s0] = n;
        g_lists[(size_t)i1 * NTOK + s1] = n;
        g_as_e[2 * n] = i0; g_as_e[2 * n + 1] = i1;
        g_as_s[2 * n] = s0; g_as_s[2 * n + 1] = s1;
        g_as_w[2 * n] = v0; g_as_w[2 * n + 1] = v1;
    }
}

// ---------------- weighted combine (deterministic, no atomics) ----------------
__global__ __launch_bounds__(256) void combine_kernel(float* __restrict__ out)
{
    const int n = blockIdx.x;
    const int t = threadIdx.x;
    const int e0 = g_as_e[2 * n],     e1 = g_as_e[2 * n + 1];
    const int s0 = g_as_s[2 * n],     s1 = g_as_s[2 * n + 1];
    const float w0 = g_as_w[2 * n],   w1 = g_as_w[2 * n + 1];
    const float* y0 = g_y + ((size_t)e0 * NTOK + s0) * DDIM;
    const float* y1 = g_y + ((size_t)e1 * NTOK + s1) * DDIM;
    float* o = out + (size_t)n * DDIM;
#pragma unroll
    for (int d = t; d < DDIM; d += 256)
        o[d] = w0 * y0[d] + w1 * y1[d];
}

// ---------------- launch ----------------
extern "C" void kernel_launch(void* const* d_in, const int* in_sizes, int n_in,
                              void* d_out, int out_size)
{
    const float* x      = (const float*)d_in[0];
    const float* r1_w   = (const float*)d_in[1];
    const float* r1_b   = (const float*)d_in[2];
    const float* ln_g   = (const float*)d_in[3];
    const float* ln_b   = (const float*)d_in[4];
    const float* r2_w   = (const float*)d_in[5];
    const float* r2_b   = (const float*)d_in[6];
    const float* temp   = (const float*)d_in[7];
    const float* rbias  = (const float*)d_in[8];
    const float* W1     = (const float*)d_in[9];
    const float* b1     = (const float*)d_in[10];
    const float* W2     = (const float*)d_in[11];
    const float* b2     = (const float*)d_in[12];
    float* out = (float*)d_out;

    void *p_h = nullptr, *p_lists = nullptr, *p_counts = nullptr;
    void *p_act = nullptr, *p_y = nullptr;
    cudaGetSymbolAddress(&p_h, g_h);
    cudaGetSymbolAddress(&p_lists, g_lists);
    cudaGetSymbolAddress(&p_counts, g_counts);
    cudaGetSymbolAddress(&p_act, g_act);
    cudaGetSymbolAddress(&p_y, g_y);

    reset_kernel<<<1, 32>>>();

    // Router GEMM1: h = x @ r1_w + r1_b   [8192 x 1024] x [1024 x 512]
    {
        dim3 grid(NTOK / BM, 1, HDIM / BN);
        gemm_kernel<<<grid, 256>>>(x, r1_w, r1_b, (float*)p_h,
                                   nullptr, nullptr,
                                   NTOK, DDIM, HDIM, DDIM, 0, 0);
    }

    // LayerNorm + GELU (in place on g_h)
    ln_gelu_kernel<<<NTOK, 256>>>(ln_g, ln_b);

    // Router GEMM2 + softmax + top2 + list building
    router2_kernel<<<NTOK, 128>>>(r2_w, r2_b, temp, rbias);

    // Expert GEMM1: act[e][slot] = actfn(x[tok] @ W1[e] + b1[e])   K=1024, N=1536
    {
        dim3 grid(NTOK / BM, EEXP, FDIM / BN);
        gemm_kernel<<<grid, 256>>>(x, W1, b1, (float*)p_act,
                                   (const int*)p_lists, (const int*)p_counts,
                                   NTOK, DDIM, FDIM, DDIM, 0, 1);
    }

    // Expert GEMM2: y[e][slot] = act[e][slot] @ W2[e] + b2[e]      K=1536, N=1024
    {
        dim3 grid(NTOK / BM, EEXP, DDIM / BN);
        gemm_kernel<<<grid, 256>>>((const float*)p_act, W2, b2, (float*)p_y,
                                   nullptr, (const int*)p_counts,
                                   NTOK, FDIM, DDIM, FDIM,
                                   (size_t)NTOK * FDIM, 0);
    }

    // Combine: out[n] = w0*y[e0][s0] + w1*y[e1][s1]
    combine_kernel<<<NTOK, 256>>>(out);
}

// round 2
// speedup vs baseline: 1.9921x; 1.9921x over previous
#include <cuda_runtime.h>
#include <math.h>
#include <cstdint>

#define NTOK 8192
#define DDIM 1024
#define HDIM 512
#define EEXP 6
#define FDIM 1536
#define LN_EPS 1e-5f

// ---------------- scratch ----------------
__device__ float g_h[(size_t)NTOK * HDIM];
__device__ int   g_counts[EEXP];
__device__ int   g_lists[(size_t)EEXP * NTOK];
__device__ int   g_as_e[NTOK * 2];
__device__ int   g_as_s[NTOK * 2];
__device__ float g_as_w[NTOK * 2];
__device__ float g_act[(size_t)EEXP * NTOK * FDIM];
__device__ float g_y[(size_t)EEXP * NTOK * DDIM];

__device__ __forceinline__ float gelu_exact(float x) {
    return 0.5f * x * (1.0f + erff(x * 0.70710678118654752440f));
}
__device__ __forceinline__ float silu(float x) {
    return x / (1.0f + expf(-x));
}

__global__ void reset_kernel() {
    if (threadIdx.x < EEXP) g_counts[threadIdx.x] = 0;
}

// ============================================================================
// fp32 SIMT GEMM (router GEMM1 only — must stay full fp32 precision)
// ============================================================================
#define BM 128
#define BN 64
#define BK 16
#define TM 8
#define TN 4

__global__ __launch_bounds__(256) void gemm_kernel(
    const float* __restrict__ A, const float* __restrict__ Bmat,
    const float* __restrict__ bias, float* __restrict__ C,
    int Mfull, int K, int Nn, int lda)
{
    const int m0 = blockIdx.x * BM;
    const int n0 = blockIdx.z * BN;

    __shared__ float As[BK][BM + 4];
    __shared__ float Bs[BK][BN];

    const int tid = threadIdx.x;
    const int tx = tid & 15;
    const int ty = tid >> 4;

    const int arow = tid >> 2;
    const int ak4  = (tid & 3) * 4;
    const float* Arow0 = A + (size_t)(m0 + arow) * lda;
    const float* Arow1 = A + (size_t)(m0 + arow + 64) * lda;

    const int bk  = tid >> 4;
    const int bn4 = (tid & 15) * 4;

    float acc[TM][TN];
#pragma unroll
    for (int i = 0; i < TM; i++)
#pragma unroll
        for (int j = 0; j < TN; j++) acc[i][j] = 0.0f;

    for (int k0 = 0; k0 < K; k0 += BK) {
        float4 a0 = *(const float4*)(Arow0 + k0 + ak4);
        float4 a1 = *(const float4*)(Arow1 + k0 + ak4);
        As[ak4 + 0][arow] = a0.x; As[ak4 + 1][arow] = a0.y;
        As[ak4 + 2][arow] = a0.z; As[ak4 + 3][arow] = a0.w;
        As[ak4 + 0][arow + 64] = a1.x; As[ak4 + 1][arow + 64] = a1.y;
        As[ak4 + 2][arow + 64] = a1.z; As[ak4 + 3][arow + 64] = a1.w;

        float4 b = *(const float4*)(Bmat + (size_t)(k0 + bk) * Nn + n0 + bn4);
        *(float4*)&Bs[bk][bn4] = b;
        __syncthreads();

#pragma unroll
        for (int k = 0; k < BK; k++) {
            float4 a01 = *(const float4*)&As[k][ty * TM];
            float4 a23 = *(const float4*)&As[k][ty * TM + 4];
            float4 bv  = *(const float4*)&Bs[k][tx * TN];
            float av[TM] = {a01.x, a01.y, a01.z, a01.w, a23.x, a23.y, a23.z, a23.w};
            float bb[TN] = {bv.x, bv.y, bv.z, bv.w};
#pragma unroll
            for (int i = 0; i < TM; i++)
#pragma unroll
                for (int j = 0; j < TN; j++)
                    acc[i][j] = fmaf(av[i], bb[j], acc[i][j]);
        }
        __syncthreads();
    }

#pragma unroll
    for (int i = 0; i < TM; i++) {
        int m = m0 + ty * TM + i;
#pragma unroll
        for (int j = 0; j < TN; j++) {
            int n = n0 + tx * TN + j;
            C[(size_t)m * Nn + n] = acc[i][j] + bias[n];
        }
    }
}

// ============================================================================
// TF32 tensor-core GEMM (expert GEMMs). 128x128x16 tiles, cp.async double buf.
// ============================================================================
#define TBM 128
#define TBN 128
#define TBK 16
#define AS_STRIDE 20            // (TBK + 4): banks (20m + k) % 32 all distinct
#define BS_STRIDE 136           // (TBN + 8): banks k*136 % 32 = 8k, disjoint

__device__ __forceinline__ uint32_t f2tf32(float f) {
    uint32_t r;
    asm("cvt.rna.tf32.f32 %0, %1;" : "=r"(r) : "f"(f));
    return r;
}

__device__ __forceinline__ void mma_tf32(float* c, const uint32_t* a, const uint32_t* b) {
    asm volatile(
        "mma.sync.aligned.m16n8k8.row.col.f32.tf32.tf32.f32 "
        "{%0,%1,%2,%3}, {%4,%5,%6,%7}, {%8,%9}, {%0,%1,%2,%3};"
        : "+f"(c[0]), "+f"(c[1]), "+f"(c[2]), "+f"(c[3])
        : "r"(a[0]), "r"(a[1]), "r"(a[2]), "r"(a[3]), "r"(b[0]), "r"(b[1]));
}

__device__ __forceinline__ void cp_async16(uint32_t dst_smem, const void* src, int src_bytes) {
    asm volatile("cp.async.cg.shared.global [%0], [%1], 16, %2;"
                 :: "r"(dst_smem), "l"(src), "r"(src_bytes));
}
__device__ __forceinline__ void cp_commit() {
    asm volatile("cp.async.commit_group;");
}
__device__ __forceinline__ void cp_wait0() {
    asm volatile("cp.async.wait_group 0;");
}

__global__ __launch_bounds__(256, 1) void tgemm_kernel(
    const float* __restrict__ A, const float* __restrict__ Bmat,
    const float* __restrict__ bias, float* __restrict__ C,
    const int* __restrict__ lists, const int* __restrict__ counts,
    int Mfull, int K, int Nn, int lda, size_t a_estride, int act_sel)
{
    const int e = blockIdx.y;
    const int Mcur = counts[e];
    const int m0 = blockIdx.x * TBM;
    if (m0 >= Mcur) return;
    const int n0 = blockIdx.z * TBN;

    const float* Ap    = A + (size_t)e * a_estride;
    const float* Bp    = Bmat + (size_t)e * (size_t)K * Nn;
    const float* biasp = bias + (size_t)e * Nn;
    float*       Cp    = C + (size_t)e * (size_t)Mfull * Nn;
    const int*   list  = lists ? (lists + (size_t)e * Mfull) : nullptr;

    __shared__ float As[2][TBM][AS_STRIDE];
    __shared__ float Bs[2][TBK][BS_STRIDE];

    const int tid  = threadIdx.x;
    const int lane = tid & 31;
    const int warp = tid >> 5;
    const int warpM = warp >> 1;   // 0..3 -> m offset *32
    const int warpN = warp & 1;    // 0..1 -> n offset *64

    // A load mapping: 2 float4 per thread. idx = tid + i*256
    // row = idx & 127, kgroup = idx >> 7 (0..3)
    const int arow0 = tid & 127;
    const int akg0  = tid >> 7;           // 0 or 1
    const int arow1 = arow0;              // (tid+256)&127 == arow0
    const int akg1  = akg0 + 2;
    const bool av0 = (m0 + arow0) < Mcur;
    const int  asrc_row0 = av0 ? (list ? list[m0 + arow0] : (m0 + arow0)) : 0;
    const float* Arowp = Ap + (size_t)asrc_row0 * lda;
    const int abytes = av0 ? 16 : 0;

    // B load mapping: 2 float4 per thread. krow = idx>>5, n4 = (idx&31)*4
    const int bk0 = tid >> 5;             // 0..7
    const int bn4 = (tid & 31) * 4;
    // second: idx = tid+256 -> krow = bk0+8, same n4

    uint32_t as_base = (uint32_t)__cvta_generic_to_shared(&As[0][0][0]);
    uint32_t bs_base = (uint32_t)__cvta_generic_to_shared(&Bs[0][0][0]);
    const uint32_t as_buf_bytes = TBM * AS_STRIDE * 4;
    const uint32_t bs_buf_bytes = TBK * BS_STRIDE * 4;

    float acc[2][8][4];
#pragma unroll
    for (int i = 0; i < 2; i++)
#pragma unroll
        for (int j = 0; j < 8; j++)
#pragma unroll
            for (int r = 0; r < 4; r++) acc[i][j][r] = 0.0f;

    const int ktiles = K / TBK;

    // prefetch tile 0 into buf 0
    {
        uint32_t ad0 = as_base + (arow0 * AS_STRIDE + akg0 * 4) * 4;
        uint32_t ad1 = as_base + (arow1 * AS_STRIDE + akg1 * 4) * 4;
        cp_async16(ad0, Arowp + akg0 * 4, abytes);
        cp_async16(ad1, Arowp + akg1 * 4, abytes);
        uint32_t bd0 = bs_base + (bk0 * BS_STRIDE + bn4) * 4;
        uint32_t bd1 = bs_base + ((bk0 + 8) * BS_STRIDE + bn4) * 4;
        cp_async16(bd0, Bp + (size_t)bk0 * Nn + n0 + bn4, 16);
        cp_async16(bd1, Bp + (size_t)(bk0 + 8) * Nn + n0 + bn4, 16);
        cp_commit();
    }

    for (int t = 0; t < ktiles; t++) {
        cp_wait0();
        __syncthreads();

        if (t + 1 < ktiles) {
            const int k0 = (t + 1) * TBK;
            const uint32_t boff = ((t + 1) & 1);
            uint32_t ad0 = as_base + boff * as_buf_bytes + (arow0 * AS_STRIDE + akg0 * 4) * 4;
            uint32_t ad1 = as_base + boff * as_buf_bytes + (arow1 * AS_STRIDE + akg1 * 4) * 4;
            cp_async16(ad0, Arowp + k0 + akg0 * 4, abytes);
            cp_async16(ad1, Arowp + k0 + akg1 * 4, abytes);
            uint32_t bd0 = bs_base + boff * bs_buf_bytes + (bk0 * BS_STRIDE + bn4) * 4;
            uint32_t bd1 = bs_base + boff * bs_buf_bytes + ((bk0 + 8) * BS_STRIDE + bn4) * 4;
            cp_async16(bd0, Bp + (size_t)(k0 + bk0) * Nn + n0 + bn4, 16);
            cp_async16(bd1, Bp + (size_t)(k0 + bk0 + 8) * Nn + n0 + bn4, 16);
            cp_commit();
        }

        const int buf = t & 1;
#pragma unroll
        for (int kk = 0; kk < TBK; kk += 8) {
            // B fragments: 8 n-tiles x 2 regs
            uint32_t bfrag[8][2];
#pragma unroll
            for (int ni = 0; ni < 8; ni++) {
                int n = warpN * 64 + ni * 8 + (lane >> 2);
                bfrag[ni][0] = f2tf32(Bs[buf][kk + (lane & 3)][n]);
                bfrag[ni][1] = f2tf32(Bs[buf][kk + 4 + (lane & 3)][n]);
            }
            // A fragments: 2 m-tiles x 4 regs
            uint32_t afrag[2][4];
#pragma unroll
            for (int mi = 0; mi < 2; mi++) {
                int m = warpM * 32 + mi * 16 + (lane >> 2);
                afrag[mi][0] = f2tf32(As[buf][m][kk + (lane & 3)]);
                afrag[mi][1] = f2tf32(As[buf][m + 8][kk + (lane & 3)]);
                afrag[mi][2] = f2tf32(As[buf][m][kk + 4 + (lane & 3)]);
                afrag[mi][3] = f2tf32(As[buf][m + 8][kk + 4 + (lane & 3)]);
            }
#pragma unroll
            for (int mi = 0; mi < 2; mi++)
#pragma unroll
                for (int ni = 0; ni < 8; ni++)
                    mma_tf32(acc[mi][ni], afrag[mi], bfrag[ni]);
        }
        __syncthreads();
    }

    // epilogue
    const bool even_e = ((e & 1) == 0);
#pragma unroll
    for (int mi = 0; mi < 2; mi++) {
        int mbase = m0 + warpM * 32 + mi * 16 + (lane >> 2);
#pragma unroll
        for (int ni = 0; ni < 8; ni++) {
            int n = n0 + warpN * 64 + ni * 8 + 2 * (lane & 3);
            float bn0 = biasp[n], bn1 = biasp[n + 1];
            // rows mbase and mbase+8
            if (mbase < Mcur) {
                float v0 = acc[mi][ni][0] + bn0;
                float v1 = acc[mi][ni][1] + bn1;
                if (act_sel == 1) {
                    v0 = even_e ? gelu_exact(v0) : silu(v0);
                    v1 = even_e ? gelu_exact(v1) : silu(v1);
                }
                *(float2*)&Cp[(size_t)mbase * Nn + n] = make_float2(v0, v1);
            }
            if (mbase + 8 < Mcur) {
                float v2 = acc[mi][ni][2] + bn0;
                float v3 = acc[mi][ni][3] + bn1;
                if (act_sel == 1) {
                    v2 = even_e ? gelu_exact(v2) : silu(v2);
                    v3 = even_e ? gelu_exact(v3) : silu(v3);
                }
                *(float2*)&Cp[(size_t)(mbase + 8) * Nn + n] = make_float2(v2, v3);
            }
        }
    }
}

// ---------------- LayerNorm + exact GELU ----------------
__global__ __launch_bounds__(256) void ln_gelu_kernel(
    const float* __restrict__ ln_g, const float* __restrict__ ln_b)
{
    const int n = blockIdx.x;
    float* row = g_h + (size_t)n * HDIM;
    const int t = threadIdx.x;
    __shared__ float red[256];

    float v0 = row[t];
    float v1 = row[t + 256];
    red[t] = v0 + v1;
    __syncthreads();
    for (int s = 128; s > 0; s >>= 1) {
        if (t < s) red[t] += red[t + s];
        __syncthreads();
    }
    float mean = red[0] * (1.0f / HDIM);
    __syncthreads();

    float d0 = v0 - mean, d1 = v1 - mean;
    red[t] = d0 * d0 + d1 * d1;
    __syncthreads();
    for (int s = 128; s > 0; s >>= 1) {
        if (t < s) red[t] += red[t + s];
        __syncthreads();
    }
    float var = red[0] * (1.0f / HDIM);
    float inv = rsqrtf(var + LN_EPS);

    float o0 = d0 * inv * ln_g[t] + ln_b[t];
    float o1 = d1 * inv * ln_g[t + 256] + ln_b[t + 256];
    row[t]       = gelu_exact(o0);
    row[t + 256] = gelu_exact(o1);
}

// ---------------- router stage 2 ----------------
__global__ __launch_bounds__(128) void router2_kernel(
    const float* __restrict__ r2w, const float* __restrict__ r2b,
    const float* __restrict__ temp, const float* __restrict__ rbias)
{
    const int n = blockIdx.x;
    const int t = threadIdx.x;
    const float* row = g_h + (size_t)n * HDIM;

    float acc[EEXP];
#pragma unroll
    for (int e = 0; e < EEXP; e++) acc[e] = 0.0f;

    for (int k = t; k < HDIM; k += 128) {
        float hv = row[k];
#pragma unroll
        for (int e = 0; e < EEXP; e++)
            acc[e] = fmaf(hv, r2w[k * EEXP + e], acc[e]);
    }

    __shared__ float red[EEXP][128];
#pragma unroll
    for (int e = 0; e < EEXP; e++) red[e][t] = acc[e];
    __syncthreads();

    __shared__ float logits[EEXP];
    if (t < EEXP) {
        float s = 0.0f;
        for (int i = 0; i < 128; i++) s += red[t][i];
        logits[t] = (s + r2b[t]) / temp[0] + rbias[t];
    }
    __syncthreads();

    if (t == 0) {
        float mx = logits[0];
#pragma unroll
        for (int e = 1; e < EEXP; e++) mx = fmaxf(mx, logits[e]);
        float p[EEXP];
        float den = 0.0f;
#pragma unroll
        for (int e = 0; e < EEXP; e++) { p[e] = expf(logits[e] - mx); den += p[e]; }
        float inv = 1.0f / den;
#pragma unroll
        for (int e = 0; e < EEXP; e++) p[e] *= inv;

        int i0 = 0; float v0 = p[0];
#pragma unroll
        for (int e = 1; e < EEXP; e++) if (p[e] > v0) { v0 = p[e]; i0 = e; }
        int i1 = -1; float v1 = -1.0f;
#pragma unroll
        for (int e = 0; e < EEXP; e++) if (e != i0 && p[e] > v1) { v1 = p[e]; i1 = e; }

        int s0 = atomicAdd(&g_counts[i0], 1);
        int s1 = atomicAdd(&g_counts[i1], 1);
        g_lists[(size_t)i0 * NTOK + s0] = n;
        g_lists[(size_t)i1 * NTOK + s1] = n;
        g_as_e[2 * n] = i0; g_as_e[2 * n + 1] = i1;
        g_as_s[2 * n] = s0; g_as_s[2 * n + 1] = s1;
        g_as_w[2 * n] = v0; g_as_w[2 * n + 1] = v1;
    }
}

// ---------------- combine ----------------
__global__ __launch_bounds__(256) void combine_kernel(float* __restrict__ out)
{
    const int n = blockIdx.x;
    const int t = threadIdx.x;
    const int e0 = g_as_e[2 * n],     e1 = g_as_e[2 * n + 1];
    const int s0 = g_as_s[2 * n],     s1 = g_as_s[2 * n + 1];
    const float w0 = g_as_w[2 * n],   w1 = g_as_w[2 * n + 1];
    const float4* y0 = (const float4*)(g_y + ((size_t)e0 * NTOK + s0) * DDIM);
    const float4* y1 = (const float4*)(g_y + ((size_t)e1 * NTOK + s1) * DDIM);
    float4* o = (float4*)(out + (size_t)n * DDIM);
    for (int d = t; d < DDIM / 4; d += 256) {
        float4 a = y0[d], b = y1[d];
        o[d] = make_float4(w0 * a.x + w1 * b.x, w0 * a.y + w1 * b.y,
                           w0 * a.z + w1 * b.z, w0 * a.w + w1 * b.w);
    }
}

// ---------------- launch ----------------
extern "C" void kernel_launch(void* const* d_in, const int* in_sizes, int n_in,
                              void* d_out, int out_size)
{
    const float* x      = (const float*)d_in[0];
    const float* r1_w   = (const float*)d_in[1];
    const float* r1_b   = (const float*)d_in[2];
    const float* ln_g   = (const float*)d_in[3];
    const float* ln_b   = (const float*)d_in[4];
    const float* r2_w   = (const float*)d_in[5];
    const float* r2_b   = (const float*)d_in[6];
    const float* temp   = (const float*)d_in[7];
    const float* rbias  = (const float*)d_in[8];
    const float* W1     = (const float*)d_in[9];
    const float* b1     = (const float*)d_in[10];
    const float* W2     = (const float*)d_in[11];
    const float* b2     = (const float*)d_in[12];
    float* out = (float*)d_out;

    void *p_h = nullptr, *p_lists = nullptr, *p_counts = nullptr;
    void *p_act = nullptr, *p_y = nullptr;
    cudaGetSymbolAddress(&p_h, g_h);
    cudaGetSymbolAddress(&p_lists, g_lists);
    cudaGetSymbolAddress(&p_counts, g_counts);
    cudaGetSymbolAddress(&p_act, g_act);
    cudaGetSymbolAddress(&p_y, g_y);

    reset_kernel<<<1, 32>>>();

    // Router GEMM1 (fp32 — precision-critical for top-k selection)
    {
        dim3 grid(NTOK / BM, 1, HDIM / BN);
        gemm_kernel<<<grid, 256>>>(x, r1_w, r1_b, (float*)p_h, NTOK, DDIM, HDIM, DDIM);
    }

    ln_gelu_kernel<<<NTOK, 256>>>(ln_g, ln_b);
    router2_kernel<<<NTOK, 128>>>(r2_w, r2_b, temp, rbias);

    // Expert GEMM1 (TF32 tensor): act = actfn(x[gather] @ W1[e] + b1[e])
    {
        dim3 grid(NTOK / TBM, EEXP, FDIM / TBN);
        tgemm_kernel<<<grid, 256>>>(x, W1, b1, (float*)p_act,
                                    (const int*)p_lists, (const int*)p_counts,
                                    NTOK, DDIM, FDIM, DDIM, 0, 1);
    }

    // Expert GEMM2 (TF32 tensor): y = act @ W2[e] + b2[e]
    {
        dim3 grid(NTOK / TBM, EEXP, DDIM / TBN);
        tgemm_kernel<<<grid, 256>>>((const float*)p_act, W2, b2, (float*)p_y,
                                    nullptr, (const int*)p_counts,
                                    NTOK, FDIM, DDIM, FDIM,
                                    (size_t)NTOK * FDIM, 0);
    }

    combine_kernel<<<NTOK, 256>>>(out);
}

// round 4
// speedup vs baseline: 2.2778x; 1.1434x over previous
#include <cuda_runtime.h>
#include <math.h>
#include <cstdint>

#define NTOK 8192
#define DDIM 1024
#define HDIM 512
#define EEXP 6
#define FDIM 1536
#define LN_EPS 1e-5f

// ---------------- scratch (device globals) ----------------
__device__ float g_h[(size_t)NTOK * HDIM];
__device__ float g_xr[(size_t)NTOK * DDIM];            // rna-rounded x
__device__ float g_r1wr[(size_t)DDIM * HDIM];          // rounded r1_w
__device__ float g_w1r[(size_t)EEXP * DDIM * FDIM];    // rounded W1
__device__ float g_w2r[(size_t)EEXP * FDIM * DDIM];    // rounded W2
__device__ int   g_counts[EEXP];
__device__ int   g_lists[(size_t)EEXP * NTOK];
__device__ int   g_as_e[NTOK * 2];
__device__ int   g_as_s[NTOK * 2];
__device__ float g_as_w[NTOK * 2];
__device__ float g_act[(size_t)EEXP * NTOK * FDIM];
__device__ float g_y[(size_t)EEXP * NTOK * DDIM];

__device__ __forceinline__ float gelu_exact(float x) {
    return 0.5f * x * (1.0f + erff(x * 0.70710678118654752440f));
}
__device__ __forceinline__ float silu(float x) {
    return x / (1.0f + expf(-x));
}
__device__ __forceinline__ float rna_tf32(float f) {
    uint32_t r;
    asm("cvt.rna.tf32.f32 %0, %1;" : "=r"(r) : "f"(f));
    return __uint_as_float(r);
}

__global__ void reset_kernel() {
    if (threadIdx.x < EEXP) g_counts[threadIdx.x] = 0;
}

// elementwise rna-round, float4 granularity
__global__ __launch_bounds__(256) void round_kernel(
    const float* __restrict__ src, float* __restrict__ dst)
{
    size_t i = (size_t)blockIdx.x * 256 + threadIdx.x;
    const float4 v = ((const float4*)src)[i];
    ((float4*)dst)[i] = make_float4(rna_tf32(v.x), rna_tf32(v.y), rna_tf32(v.z), rna_tf32(v.w));
}

// ============================================================================
// TF32 tensor-core GEMM (mma.sync legacy path — sm_103 base target).
// 128x128x16 tiles, cp.async double-buffered. Inputs PRE-ROUNDED to tf32.
// ============================================================================
#define TBM 128
#define TBN 128
#define TBK 16
#define AS_STRIDE 20
#define BS_STRIDE 136

__device__ __forceinline__ void mma_tf32(float* c, const uint32_t* a, const uint32_t* b) {
    asm volatile(
        "mma.sync.aligned.m16n8k8.row.col.f32.tf32.tf32.f32 "
        "{%0,%1,%2,%3}, {%4,%5,%6,%7}, {%8,%9}, {%0,%1,%2,%3};"
        : "+f"(c[0]), "+f"(c[1]), "+f"(c[2]), "+f"(c[3])
        : "r"(a[0]), "r"(a[1]), "r"(a[2]), "r"(a[3]), "r"(b[0]), "r"(b[1]));
}

__device__ __forceinline__ void cp_async16(uint32_t dst_smem, const void* src, int src_bytes) {
    asm volatile("cp.async.cg.shared.global [%0], [%1], 16, %2;"
                 :: "r"(dst_smem), "l"(src), "r"(src_bytes));
}
__device__ __forceinline__ void cp_commit() { asm volatile("cp.async.commit_group;"); }
__device__ __forceinline__ void cp_wait0() { asm volatile("cp.async.wait_group 0;"); }

__global__ __launch_bounds__(256, 2) void tgemm_kernel(
    const float* __restrict__ A, const float* __restrict__ Bmat,
    const float* __restrict__ bias, float* __restrict__ C,
    const int* __restrict__ lists, const int* __restrict__ counts,
    int Mfull, int K, int Nn, int lda, size_t a_estride, int act_sel)
{
    const int e = blockIdx.y;
    const int Mcur = counts ? counts[e] : Mfull;
    const int m0 = blockIdx.x * TBM;
    if (m0 >= Mcur) return;
    const int n0 = blockIdx.z * TBN;

    const float* Ap    = A + (size_t)e * a_estride;
    const float* Bp    = Bmat + (size_t)e * (size_t)K * Nn;
    const float* biasp = bias + (size_t)e * Nn;
    float*       Cp    = C + (size_t)e * (size_t)Mfull * Nn;
    const int*   list  = lists ? (lists + (size_t)e * Mfull) : nullptr;

    __shared__ float As[2][TBM][AS_STRIDE];
    __shared__ float Bs[2][TBK][BS_STRIDE];

    const int tid  = threadIdx.x;
    const int lane = tid & 31;
    const int warp = tid >> 5;
    const int warpM = warp >> 1;
    const int warpN = warp & 1;

    const int arow0 = tid & 127;
    const int akg0  = tid >> 7;
    const int akg1  = akg0 + 2;
    const bool av0 = (m0 + arow0) < Mcur;
    const int  asrc_row0 = av0 ? (list ? list[m0 + arow0] : (m0 + arow0)) : 0;
    const float* Arowp = Ap + (size_t)asrc_row0 * lda;
    const int abytes = av0 ? 16 : 0;

    const int bk0 = tid >> 5;
    const int bn4 = (tid & 31) * 4;

    uint32_t as_base = (uint32_t)__cvta_generic_to_shared(&As[0][0][0]);
    uint32_t bs_base = (uint32_t)__cvta_generic_to_shared(&Bs[0][0][0]);
    const uint32_t as_buf_bytes = TBM * AS_STRIDE * 4;
    const uint32_t bs_buf_bytes = TBK * BS_STRIDE * 4;

    float acc[2][8][4];
#pragma unroll
    for (int i = 0; i < 2; i++)
#pragma unroll
        for (int j = 0; j < 8; j++)
#pragma unroll
            for (int r = 0; r < 4; r++) acc[i][j][r] = 0.0f;

    const int ktiles = K / TBK;

    {
        uint32_t ad0 = as_base + (arow0 * AS_STRIDE + akg0 * 4) * 4;
        uint32_t ad1 = as_base + (arow0 * AS_STRIDE + akg1 * 4) * 4;
        cp_async16(ad0, Arowp + akg0 * 4, abytes);
        cp_async16(ad1, Arowp + akg1 * 4, abytes);
        uint32_t bd0 = bs_base + (bk0 * BS_STRIDE + bn4) * 4;
        uint32_t bd1 = bs_base + ((bk0 + 8) * BS_STRIDE + bn4) * 4;
        cp_async16(bd0, Bp + (size_t)bk0 * Nn + n0 + bn4, 16);
        cp_async16(bd1, Bp + (size_t)(bk0 + 8) * Nn + n0 + bn4, 16);
        cp_commit();
    }

    for (int t = 0; t < ktiles; t++) {
        cp_wait0();
        __syncthreads();

        if (t + 1 < ktiles) {
            const int k0 = (t + 1) * TBK;
            const uint32_t boff = ((t + 1) & 1);
            uint32_t ad0 = as_base + boff * as_buf_bytes + (arow0 * AS_STRIDE + akg0 * 4) * 4;
            uint32_t ad1 = as_base + boff * as_buf_bytes + (arow0 * AS_STRIDE + akg1 * 4) * 4;
            cp_async16(ad0, Arowp + k0 + akg0 * 4, abytes);
            cp_async16(ad1, Arowp + k0 + akg1 * 4, abytes);
            uint32_t bd0 = bs_base + boff * bs_buf_bytes + (bk0 * BS_STRIDE + bn4) * 4;
            uint32_t bd1 = bs_base + boff * bs_buf_bytes + ((bk0 + 8) * BS_STRIDE + bn4) * 4;
            cp_async16(bd0, Bp + (size_t)(k0 + bk0) * Nn + n0 + bn4, 16);
            cp_async16(bd1, Bp + (size_t)(k0 + bk0 + 8) * Nn + n0 + bn4, 16);
            cp_commit();
        }

        const int buf = t & 1;
#pragma unroll
        for (int kk = 0; kk < TBK; kk += 8) {
            uint32_t bfrag[8][2];
#pragma unroll
            for (int ni = 0; ni < 8; ni++) {
                int n = warpN * 64 + ni * 8 + (lane >> 2);
                bfrag[ni][0] = __float_as_uint(Bs[buf][kk + (lane & 3)][n]);
                bfrag[ni][1] = __float_as_uint(Bs[buf][kk + 4 + (lane & 3)][n]);
            }
            uint32_t afrag[2][4];
#pragma unroll
            for (int mi = 0; mi < 2; mi++) {
                int m = warpM * 32 + mi * 16 + (lane >> 2);
                afrag[mi][0] = __float_as_uint(As[buf][m][kk + (lane & 3)]);
                afrag[mi][1] = __float_as_uint(As[buf][m + 8][kk + (lane & 3)]);
                afrag[mi][2] = __float_as_uint(As[buf][m][kk + 4 + (lane & 3)]);
                afrag[mi][3] = __float_as_uint(As[buf][m + 8][kk + 4 + (lane & 3)]);
            }
#pragma unroll
            for (int mi = 0; mi < 2; mi++)
#pragma unroll
                for (int ni = 0; ni < 8; ni++)
                    mma_tf32(acc[mi][ni], afrag[mi], bfrag[ni]);
        }
        __syncthreads();
    }

    const bool even_e = ((e & 1) == 0);
#pragma unroll
    for (int mi = 0; mi < 2; mi++) {
        int mbase = m0 + warpM * 32 + mi * 16 + (lane >> 2);
#pragma unroll
        for (int ni = 0; ni < 8; ni++) {
            int n = n0 + warpN * 64 + ni * 8 + 2 * (lane & 3);
            float bn0 = biasp[n], bn1 = biasp[n + 1];
            if (mbase < Mcur) {
                float v0 = acc[mi][ni][0] + bn0;
                float v1 = acc[mi][ni][1] + bn1;
                if (act_sel == 1) {
                    v0 = even_e ? gelu_exact(v0) : silu(v0);
                    v1 = even_e ? gelu_exact(v1) : silu(v1);
                    v0 = rna_tf32(v0); v1 = rna_tf32(v1);
                }
                *(float2*)&Cp[(size_t)mbase * Nn + n] = make_float2(v0, v1);
            }
            if (mbase + 8 < Mcur) {
                float v2 = acc[mi][ni][2] + bn0;
                float v3 = acc[mi][ni][3] + bn1;
                if (act_sel == 1) {
                    v2 = even_e ? gelu_exact(v2) : silu(v2);
                    v3 = even_e ? gelu_exact(v3) : silu(v3);
                    v2 = rna_tf32(v2); v3 = rna_tf32(v3);
                }
                *(float2*)&Cp[(size_t)(mbase + 8) * Nn + n] = make_float2(v2, v3);
            }
        }
    }
}

// ---------------- LayerNorm + exact GELU ----------------
__global__ __launch_bounds__(256) void ln_gelu_kernel(
    const float* __restrict__ ln_g, const float* __restrict__ ln_b)
{
    const int n = blockIdx.x;
    float* row = g_h + (size_t)n * HDIM;
    const int t = threadIdx.x;
    __shared__ float red[256];

    float v0 = row[t];
    float v1 = row[t + 256];
    red[t] = v0 + v1;
    __syncthreads();
    for (int s = 128; s > 0; s >>= 1) {
        if (t < s) red[t] += red[t + s];
        __syncthreads();
    }
    float mean = red[0] * (1.0f / HDIM);
    __syncthreads();

    float d0 = v0 - mean, d1 = v1 - mean;
    red[t] = d0 * d0 + d1 * d1;
    __syncthreads();
    for (int s = 128; s > 0; s >>= 1) {
        if (t < s) red[t] += red[t + s];
        __syncthreads();
    }
    float var = red[0] * (1.0f / HDIM);
    float inv = rsqrtf(var + LN_EPS);

    float o0 = d0 * inv * ln_g[t] + ln_b[t];
    float o1 = d1 * inv * ln_g[t + 256] + ln_b[t + 256];
    row[t]       = gelu_exact(o0);
    row[t + 256] = gelu_exact(o1);
}

// ---------------- router stage 2 (shuffle-reduced) ----------------
__global__ __launch_bounds__(128) void router2_kernel(
    const float* __restrict__ r2w, const float* __restrict__ r2b,
    const float* __restrict__ temp, const float* __restrict__ rbias)
{
    const int n = blockIdx.x;
    const int t = threadIdx.x;
    const int lane = t & 31, warp = t >> 5;
    const float* row = g_h + (size_t)n * HDIM;

    float acc[EEXP];
#pragma unroll
    for (int e = 0; e < EEXP; e++) acc[e] = 0.0f;
#pragma unroll
    for (int kk = 0; kk < HDIM / 128; kk++) {
        int k = t + kk * 128;
        float hv = row[k];
#pragma unroll
        for (int e = 0; e < EEXP; e++)
            acc[e] = fmaf(hv, r2w[k * EEXP + e], acc[e]);
    }
#pragma unroll
    for (int e = 0; e < EEXP; e++)
#pragma unroll
        for (int o = 16; o > 0; o >>= 1)
            acc[e] += __shfl_xor_sync(0xFFFFFFFF, acc[e], o);

    __shared__ float red[EEXP][4];
    if (lane == 0)
#pragma unroll
        for (int e = 0; e < EEXP; e++) red[e][warp] = acc[e];
    __syncthreads();

    if (t == 0) {
        float logits[EEXP];
        float tinv = 1.0f / temp[0];
#pragma unroll
        for (int e = 0; e < EEXP; e++)
            logits[e] = (red[e][0] + red[e][1] + red[e][2] + red[e][3] + r2b[e]) * tinv + rbias[e];

        float mx = logits[0];
#pragma unroll
        for (int e = 1; e < EEXP; e++) mx = fmaxf(mx, logits[e]);
        float p[EEXP], den = 0.0f;
#pragma unroll
        for (int e = 0; e < EEXP; e++) { p[e] = expf(logits[e] - mx); den += p[e]; }
        float inv = 1.0f / den;
#pragma unroll
        for (int e = 0; e < EEXP; e++) p[e] *= inv;

        int i0 = 0; float v0 = p[0];
#pragma unroll
        for (int e = 1; e < EEXP; e++) if (p[e] > v0) { v0 = p[e]; i0 = e; }
        int i1 = -1; float v1 = -1.0f;
#pragma unroll
        for (int e = 0; e < EEXP; e++) if (e != i0 && p[e] > v1) { v1 = p[e]; i1 = e; }

        int s0 = atomicAdd(&g_counts[i0], 1);
        int s1 = atomicAdd(&g_counts[i1], 1);
        g_lists[(size_t)i0 * NTOK + s0] = n;
        g_lists[(size_t)i1 * NTOK + s1] = n;
        g_as_e[2 * n] = i0; g_as_e[2 * n + 1] = i1;
        g_as_s[2 * n] = s0; g_as_s[2 * n + 1] = s1;
        g_as_w[2 * n] = v0; g_as_w[2 * n + 1] = v1;
    }
}

// ---------------- combine ----------------
__global__ __launch_bounds__(256) void combine_kernel(float* __restrict__ out)
{
    const int n = blockIdx.x;
    const int t = threadIdx.x;
    const int e0 = g_as_e[2 * n],   e1 = g_as_e[2 * n + 1];
    const int s0 = g_as_s[2 * n],   s1 = g_as_s[2 * n + 1];
    const float w0 = g_as_w[2 * n], w1 = g_as_w[2 * n + 1];
    const float4* y0 = (const float4*)(g_y + ((size_t)e0 * NTOK + s0) * DDIM);
    const float4* y1 = (const float4*)(g_y + ((size_t)e1 * NTOK + s1) * DDIM);
    float4* o = (float4*)(out + (size_t)n * DDIM);
    for (int d = t; d < DDIM / 4; d += 256) {
        float4 a = y0[d], b = y1[d];
        o[d] = make_float4(w0 * a.x + w1 * b.x, w0 * a.y + w1 * b.y,
                           w0 * a.z + w1 * b.z, w0 * a.w + w1 * b.w);
    }
}

// ---------------- launch ----------------
extern "C" void kernel_launch(void* const* d_in, const int* in_sizes, int n_in,
                              void* d_out, int out_size)
{
    const float* x      = (const float*)d_in[0];
    const float* r1_w   = (const float*)d_in[1];
    const float* r1_b   = (const float*)d_in[2];
    const float* ln_g   = (const float*)d_in[3];
    const float* ln_b   = (const float*)d_in[4];
    const float* r2_w   = (const float*)d_in[5];
    const float* r2_b   = (const float*)d_in[6];
    const float* temp   = (const float*)d_in[7];
    const float* rbias  = (const float*)d_in[8];
    const float* W1     = (const float*)d_in[9];
    const float* b1     = (const float*)d_in[10];
    const float* W2     = (const float*)d_in[11];
    const float* b2     = (const float*)d_in[12];
    float* out = (float*)d_out;

    void *p_h, *p_xr, *p_r1wr, *p_w1r, *p_w2r, *p_lists, *p_counts, *p_act, *p_y;
    cudaGetSymbolAddress(&p_h, g_h);
    cudaGetSymbolAddress(&p_xr, g_xr);
    cudaGetSymbolAddress(&p_r1wr, g_r1wr);
    cudaGetSymbolAddress(&p_w1r, g_w1r);
    cudaGetSymbolAddress(&p_w2r, g_w2r);
    cudaGetSymbolAddress(&p_lists, g_lists);
    cudaGetSymbolAddress(&p_counts, g_counts);
    cudaGetSymbolAddress(&p_act, g_act);
    cudaGetSymbolAddress(&p_y, g_y);

    reset_kernel<<<1, 32>>>();

    // pre-round everything the tensor GEMMs consume
    round_kernel<<<(NTOK * DDIM) / 1024, 256>>>(x, (float*)p_xr);
    round_kernel<<<(DDIM * HDIM) / 1024, 256>>>(r1_w, (float*)p_r1wr);
    round_kernel<<<(EEXP * DDIM * FDIM) / 1024, 256>>>(W1, (float*)p_w1r);
    round_kernel<<<(EEXP * FDIM * DDIM) / 1024, 256>>>(W2, (float*)p_w2r);

    // Router GEMM1 (tf32 tensor): h = x @ r1_w + r1_b
    {
        dim3 grid(NTOK / TBM, 1, HDIM / TBN);
        tgemm_kernel<<<grid, 256>>>((const float*)p_xr, (const float*)p_r1wr, r1_b,
                                    (float*)p_h, nullptr, nullptr,
                                    NTOK, DDIM, HDIM, DDIM, 0, 0);
    }

    ln_gelu_kernel<<<NTOK, 256>>>(ln_g, ln_b);
    router2_kernel<<<NTOK, 128>>>(r2_w, r2_b, temp, rbias);

    // Expert GEMM1 (tf32 tensor): act = rna(actfn(x[gather] @ W1[e] + b1[e]))
    {
        dim3 grid(NTOK / TBM, EEXP, FDIM / TBN);
        tgemm_kernel<<<grid, 256>>>((const float*)p_xr, (const float*)p_w1r, b1,
                                    (float*)p_act, (const int*)p_lists, (const int*)p_counts,
                                    NTOK, DDIM, FDIM, DDIM, 0, 1);
    }

    // Expert GEMM2 (tf32 tensor): y = act @ W2[e] + b2[e]
    {
        dim3 grid(NTOK / TBM, EEXP, DDIM / TBN);
        tgemm_kernel<<<grid, 256>>>((const float*)p_act, (const float*)p_w2r, b2,
                                    (float*)p_y, nullptr, (const int*)p_counts,
                                    NTOK, FDIM, DDIM, FDIM,
                                    (size_t)NTOK * FDIM, 0);
    }

    combine_kernel<<<NTOK, 256>>>(out);
}

// round 5
// speedup vs baseline: 2.9475x; 1.2940x over previous
#include <cuda_runtime.h>
#include <math.h>
#include <cstdint>

#define NTOK 8192
#define DDIM 1024
#define HDIM 512
#define EEXP 6
#define FDIM 1536
#define LN_EPS 1e-5f

// ---------------- scratch (device globals) ----------------
__device__ float g_h[(size_t)NTOK * HDIM];
__device__ float g_xr[(size_t)NTOK * DDIM];            // rna-rounded x
__device__ float g_r1wt[(size_t)HDIM * DDIM];          // r1_w^T rounded  [H][D]
__device__ float g_w1t[(size_t)EEXP * FDIM * DDIM];    // W1^T rounded    [E][F][D]
__device__ float g_w2t[(size_t)EEXP * DDIM * FDIM];    // W2^T rounded    [E][D][F]
__device__ int   g_counts[EEXP];
__device__ int   g_lists[(size_t)EEXP * NTOK];
__device__ int   g_as_e[NTOK * 2];
__device__ int   g_as_s[NTOK * 2];
__device__ float g_as_w[NTOK * 2];
__device__ float g_act[(size_t)EEXP * NTOK * FDIM];
__device__ float g_y[(size_t)EEXP * NTOK * DDIM];

__device__ __forceinline__ float gelu_exact(float x) {
    return 0.5f * x * (1.0f + erff(x * 0.70710678118654752440f));
}
__device__ __forceinline__ float silu(float x) {
    return x / (1.0f + expf(-x));
}
__device__ __forceinline__ float rna_tf32(float f) {
    uint32_t r;
    asm("cvt.rna.tf32.f32 %0, %1;" : "=r"(r) : "f"(f));
    return __uint_as_float(r);
}

__global__ void reset_kernel() {
    if (threadIdx.x < EEXP) g_counts[threadIdx.x] = 0;
}

// elementwise rna-round, float4 granularity
__global__ __launch_bounds__(256) void round_kernel(
    const float* __restrict__ src, float* __restrict__ dst)
{
    size_t i = (size_t)blockIdx.x * 256 + threadIdx.x;
    const float4 v = ((const float4*)src)[i];
    ((float4*)dst)[i] = make_float4(rna_tf32(v.x), rna_tf32(v.y), rna_tf32(v.z), rna_tf32(v.w));
}

// transpose [R,C] -> [C,R] with rna rounding; batched over z
__global__ __launch_bounds__(256) void transpose_rna_kernel(
    const float* __restrict__ src, float* __restrict__ dst, int R, int C)
{
    __shared__ float tile[32][33];
    const int e = blockIdx.z;
    src += (size_t)e * R * C;
    dst += (size_t)e * R * C;
    const int c0 = blockIdx.x * 32, r0 = blockIdx.y * 32;
    const int tx = threadIdx.x & 31, ty = threadIdx.x >> 5;
#pragma unroll
    for (int i = ty; i < 32; i += 8)
        tile[i][tx] = src[(size_t)(r0 + i) * C + c0 + tx];
    __syncthreads();
#pragma unroll
    for (int i = ty; i < 32; i += 8)
        dst[(size_t)(c0 + i) * R + r0 + tx] = rna_tf32(tile[tx][i]);
}

// ============================================================================
// TF32 tensor GEMM, ldmatrix operand path.
// C[e] = act( A[gather] @ Bt^T + bias ).  A: [rows][K] row-major (pre-rounded),
// Bt: [Nn][K] row-major (pre-transposed+rounded). 128x128x16 tiles, cp.async 2-buf.
// ============================================================================
#define TBM 128
#define TBN 128
#define TBK 16
#define TS 20   // padded stride (floats): banks 20r mod 32 all-distinct over 8 rows

__device__ __forceinline__ void mma_tf32(float* c, const uint32_t* a, const uint32_t* b) {
    asm volatile(
        "mma.sync.aligned.m16n8k8.row.col.f32.tf32.tf32.f32 "
        "{%0,%1,%2,%3}, {%4,%5,%6,%7}, {%8,%9}, {%0,%1,%2,%3};"
        : "+f"(c[0]), "+f"(c[1]), "+f"(c[2]), "+f"(c[3])
        : "r"(a[0]), "r"(a[1]), "r"(a[2]), "r"(a[3]), "r"(b[0]), "r"(b[1]));
}
__device__ __forceinline__ void ldsm_x4(uint32_t* r, uint32_t addr) {
    asm volatile("ldmatrix.sync.aligned.m8n8.x4.shared.b16 {%0,%1,%2,%3}, [%4];"
                 : "=r"(r[0]), "=r"(r[1]), "=r"(r[2]), "=r"(r[3]) : "r"(addr));
}
__device__ __forceinline__ void cp_async16(uint32_t dst_smem, const void* src, int src_bytes) {
    asm volatile("cp.async.cg.shared.global [%0], [%1], 16, %2;"
                 :: "r"(dst_smem), "l"(src), "r"(src_bytes));
}
__device__ __forceinline__ void cp_commit() { asm volatile("cp.async.commit_group;"); }
__device__ __forceinline__ void cp_wait0() { asm volatile("cp.async.wait_group 0;"); }

__global__ __launch_bounds__(256, 2) void tgemm_kernel(
    const float* __restrict__ A, const float* __restrict__ Bt,
    const float* __restrict__ bias, float* __restrict__ C,
    const int* __restrict__ lists, const int* __restrict__ counts,
    int Mfull, int K, int Nn, int lda, size_t a_estride, int act_sel)
{
    const int e = blockIdx.y;
    const int Mcur = counts ? counts[e] : Mfull;
    const int m0 = blockIdx.x * TBM;
    if (m0 >= Mcur) return;
    const int n0 = blockIdx.z * TBN;

    const float* Ap    = A + (size_t)e * a_estride;
    const float* Btp   = Bt + (size_t)e * (size_t)K * Nn;
    const float* biasp = bias + (size_t)e * Nn;
    float*       Cp    = C + (size_t)e * (size_t)Mfull * Nn;
    const int*   list  = lists ? (lists + (size_t)e * Mfull) : nullptr;

    __shared__ float As[2][TBM][TS];
    __shared__ float Bs[2][TBN][TS];

    const int tid  = threadIdx.x;
    const int lane = tid & 31;
    const int warp = tid >> 5;
    const int warpM = warp >> 1;   // *32 rows
    const int warpN = warp & 1;    // *64 cols

    // ---- load mapping: 512 16B-chunks per operand per stage; 2 chunks/thread
    // chunk c: row = c>>2 (0..127), kq = c&3 (16B unit)
    const int r0i = tid >> 2;            // rows r0i and r0i+64
    const int kq  = (tid & 3) * 4;       // float offset
    const bool av0 = (m0 + r0i) < Mcur;
    const bool av1 = (m0 + r0i + 64) < Mcur;
    const int tok0 = av0 ? (list ? list[m0 + r0i] : (m0 + r0i)) : 0;
    const int tok1 = av1 ? (list ? list[m0 + r0i + 64] : (m0 + r0i + 64)) : 0;
    const float* a_src0 = Ap + (size_t)tok0 * lda + kq;
    const float* a_src1 = Ap + (size_t)tok1 * lda + kq;
    const int ab0 = av0 ? 16 : 0, ab1 = av1 ? 16 : 0;
    const float* b_src0 = Btp + (size_t)(n0 + r0i) * K + kq;
    const float* b_src1 = Btp + (size_t)(n0 + r0i + 64) * K + kq;

    uint32_t as_base = (uint32_t)__cvta_generic_to_shared(&As[0][0][0]);
    uint32_t bs_base = (uint32_t)__cvta_generic_to_shared(&Bs[0][0][0]);
    const uint32_t ABYTES = TBM * TS * 4;
    const uint32_t BBYTES = TBN * TS * 4;
    const uint32_t a_d0 = (r0i * TS + kq) * 4;
    const uint32_t a_d1 = ((r0i + 64) * TS + kq) * 4;

    // ---- ldmatrix per-lane row/col offsets
    const int lmA_r = (lane & 7) + ((lane >> 3) & 1) * 8;    // a0/a1 row split
    const int lmA_c = ((lane >> 4) & 1) * 4;                 // a2/a3 k split
    const int lmB_r = (lane & 7) + ((lane >> 4) & 1) * 8;    // ntile pair split
    const int lmB_c = ((lane >> 3) & 1) * 4;                 // b0/b1 k split

    float acc[2][8][4];
#pragma unroll
    for (int i = 0; i < 2; i++)
#pragma unroll
        for (int j = 0; j < 8; j++)
#pragma unroll
            for (int r = 0; r < 4; r++) acc[i][j][r] = 0.0f;

    const int ktiles = K / TBK;

    // prefetch tile 0 -> stage 0
    cp_async16(as_base + a_d0, a_src0, ab0);
    cp_async16(as_base + a_d1, a_src1, ab1);
    cp_async16(bs_base + a_d0, b_src0, 16);
    cp_async16(bs_base + a_d1, b_src1, 16);
    cp_commit();

    for (int t = 0; t < ktiles; t++) {
        cp_wait0();
        __syncthreads();

        if (t + 1 < ktiles) {
            const int k0 = (t + 1) * TBK;
            const uint32_t bo = ((t + 1) & 1);
            cp_async16(as_base + bo * ABYTES + a_d0, a_src0 + k0, ab0);
            cp_async16(as_base + bo * ABYTES + a_d1, a_src1 + k0, ab1);
            cp_async16(bs_base + bo * BBYTES + a_d0, b_src0 + k0, 16);
            cp_async16(bs_base + bo * BBYTES + a_d1, b_src1 + k0, 16);
            cp_commit();
        }

        const uint32_t abuf = as_base + (t & 1) * ABYTES;
        const uint32_t bbuf = bs_base + (t & 1) * BBYTES;
#pragma unroll
        for (int kk = 0; kk < TBK; kk += 8) {
            uint32_t afrag[2][4];
#pragma unroll
            for (int mi = 0; mi < 2; mi++) {
                uint32_t addr = abuf +
                    ((warpM * 32 + mi * 16 + lmA_r) * TS + kk + lmA_c) * 4;
                ldsm_x4(afrag[mi], addr);
            }
            uint32_t bfrag[8][2];
#pragma unroll
            for (int j = 0; j < 4; j++) {
                uint32_t addr = bbuf +
                    ((warpN * 64 + j * 16 + lmB_r) * TS + kk + lmB_c) * 4;
                uint32_t r4[4];
                ldsm_x4(r4, addr);
                bfrag[2 * j][0] = r4[0]; bfrag[2 * j][1] = r4[1];
                bfrag[2 * j + 1][0] = r4[2]; bfrag[2 * j + 1][1] = r4[3];
            }
#pragma unroll
            for (int mi = 0; mi < 2; mi++)
#pragma unroll
                for (int ni = 0; ni < 8; ni++)
                    mma_tf32(acc[mi][ni], afrag[mi], bfrag[ni]);
        }
        __syncthreads();
    }

    const bool even_e = ((e & 1) == 0);
#pragma unroll
    for (int mi = 0; mi < 2; mi++) {
        int mbase = m0 + warpM * 32 + mi * 16 + (lane >> 2);
#pragma unroll
        for (int ni = 0; ni < 8; ni++) {
            int n = n0 + warpN * 64 + ni * 8 + 2 * (lane & 3);
            float bn0 = biasp[n], bn1 = biasp[n + 1];
            if (mbase < Mcur) {
                float v0 = acc[mi][ni][0] + bn0;
                float v1 = acc[mi][ni][1] + bn1;
                if (act_sel == 1) {
                    v0 = even_e ? gelu_exact(v0) : silu(v0);
                    v1 = even_e ? gelu_exact(v1) : silu(v1);
                    v0 = rna_tf32(v0); v1 = rna_tf32(v1);
                }
                *(float2*)&Cp[(size_t)mbase * Nn + n] = make_float2(v0, v1);
            }
            if (mbase + 8 < Mcur) {
                float v2 = acc[mi][ni][2] + bn0;
                float v3 = acc[mi][ni][3] + bn1;
                if (act_sel == 1) {
                    v2 = even_e ? gelu_exact(v2) : silu(v2);
                    v3 = even_e ? gelu_exact(v3) : silu(v3);
                    v2 = rna_tf32(v2); v3 = rna_tf32(v3);
                }
                *(float2*)&Cp[(size_t)(mbase + 8) * Nn + n] = make_float2(v2, v3);
            }
        }
    }
}

// ---------------- LayerNorm + exact GELU ----------------
__global__ __launch_bounds__(256) void ln_gelu_kernel(
    const float* __restrict__ ln_g, const float* __restrict__ ln_b)
{
    const int n = blockIdx.x;
    float* row = g_h + (size_t)n * HDIM;
    const int t = threadIdx.x;
    __shared__ float red[256];

    float v0 = row[t];
    float v1 = row[t + 256];
    red[t] = v0 + v1;
    __syncthreads();
    for (int s = 128; s > 0; s >>= 1) {
        if (t < s) red[t] += red[t + s];
        __syncthreads();
    }
    float mean = red[0] * (1.0f / HDIM);
    __syncthreads();

    float d0 = v0 - mean, d1 = v1 - mean;
    red[t] = d0 * d0 + d1 * d1;
    __syncthreads();
    for (int s = 128; s > 0; s >>= 1) {
        if (t < s) red[t] += red[t + s];
        __syncthreads();
    }
    float var = red[0] * (1.0f / HDIM);
    float inv = rsqrtf(var + LN_EPS);

    float o0 = d0 * inv * ln_g[t] + ln_b[t];
    float o1 = d1 * inv * ln_g[t + 256] + ln_b[t + 256];
    row[t]       = gelu_exact(o0);
    row[t + 256] = gelu_exact(o1);
}

// ---------------- router stage 2 (shuffle-reduced) ----------------
__global__ __launch_bounds__(128) void router2_kernel(
    const float* __restrict__ r2w, const float* __restrict__ r2b,
    const float* __restrict__ temp, const float* __restrict__ rbias)
{
    const int n = blockIdx.x;
    const int t = threadIdx.x;
    const int lane = t & 31, warp = t >> 5;
    const float* row = g_h + (size_t)n * HDIM;

    float acc[EEXP];
#pragma unroll
    for (int e = 0; e < EEXP; e++) acc[e] = 0.0f;
#pragma unroll
    for (int kk = 0; kk < HDIM / 128; kk++) {
        int k = t + kk * 128;
        float hv = row[k];
#pragma unroll
        for (int e = 0; e < EEXP; e++)
            acc[e] = fmaf(hv, r2w[k * EEXP + e], acc[e]);
    }
#pragma unroll
    for (int e = 0; e < EEXP; e++)
#pragma unroll
        for (int o = 16; o > 0; o >>= 1)
            acc[e] += __shfl_xor_sync(0xFFFFFFFF, acc[e], o);

    __shared__ float red[EEXP][4];
    if (lane == 0)
#pragma unroll
        for (int e = 0; e < EEXP; e++) red[e][warp] = acc[e];
    __syncthreads();

    if (t == 0) {
        float logits[EEXP];
        float tinv = 1.0f / temp[0];
#pragma unroll
        for (int e = 0; e < EEXP; e++)
            logits[e] = (red[e][0] + red[e][1] + red[e][2] + red[e][3] + r2b[e]) * tinv + rbias[e];

        float mx = logits[0];
#pragma unroll
        for (int e = 1; e < EEXP; e++) mx = fmaxf(mx, logits[e]);
        float p[EEXP], den = 0.0f;
#pragma unroll
        for (int e = 0; e < EEXP; e++) { p[e] = expf(logits[e] - mx); den += p[e]; }
        float inv = 1.0f / den;
#pragma unroll
        for (int e = 0; e < EEXP; e++) p[e] *= inv;

        int i0 = 0; float v0 = p[0];
#pragma unroll
        for (int e = 1; e < EEXP; e++) if (p[e] > v0) { v0 = p[e]; i0 = e; }
        int i1 = -1; float v1 = -1.0f;
#pragma unroll
        for (int e = 0; e < EEXP; e++) if (e != i0 && p[e] > v1) { v1 = p[e]; i1 = e; }

        int s0 = atomicAdd(&g_counts[i0], 1);
        int s1 = atomicAdd(&g_counts[i1], 1);
        g_lists[(size_t)i0 * NTOK + s0] = n;
        g_lists[(size_t)i1 * NTOK + s1] = n;
        g_as_e[2 * n] = i0; g_as_e[2 * n + 1] = i1;
        g_as_s[2 * n] = s0; g_as_s[2 * n + 1] = s1;
        g_as_w[2 * n] = v0; g_as_w[2 * n + 1] = v1;
    }
}

// ---------------- combine ----------------
__global__ __launch_bounds__(256) void combine_kernel(float* __restrict__ out)
{
    const int n = blockIdx.x;
    const int t = threadIdx.x;
    const int e0 = g_as_e[2 * n],   e1 = g_as_e[2 * n + 1];
    const int s0 = g_as_s[2 * n],   s1 = g_as_s[2 * n + 1];
    const float w0 = g_as_w[2 * n], w1 = g_as_w[2 * n + 1];
    const float4* y0 = (const float4*)(g_y + ((size_t)e0 * NTOK + s0) * DDIM);
    const float4* y1 = (const float4*)(g_y + ((size_t)e1 * NTOK + s1) * DDIM);
    float4* o = (float4*)(out + (size_t)n * DDIM);
    for (int d = t; d < DDIM / 4; d += 256) {
        float4 a = y0[d], b = y1[d];
        o[d] = make_float4(w0 * a.x + w1 * b.x, w0 * a.y + w1 * b.y,
                           w0 * a.z + w1 * b.z, w0 * a.w + w1 * b.w);
    }
}

// ---------------- launch ----------------
extern "C" void kernel_launch(void* const* d_in, const int* in_sizes, int n_in,
                              void* d_out, int out_size)
{
    const float* x      = (const float*)d_in[0];
    const float* r1_w   = (const float*)d_in[1];
    const float* r1_b   = (const float*)d_in[2];
    const float* ln_g   = (const float*)d_in[3];
    const float* ln_b   = (const float*)d_in[4];
    const float* r2_w   = (const float*)d_in[5];
    const float* r2_b   = (const float*)d_in[6];
    const float* temp   = (const float*)d_in[7];
    const float* rbias  = (const float*)d_in[8];
    const float* W1     = (const float*)d_in[9];
    const float* b1     = (const float*)d_in[10];
    const float* W2     = (const float*)d_in[11];
    const float* b2     = (const float*)d_in[12];
    float* out = (float*)d_out;

    void *p_h, *p_xr, *p_r1wt, *p_w1t, *p_w2t, *p_lists, *p_counts, *p_act, *p_y;
    cudaGetSymbolAddress(&p_h, g_h);
    cudaGetSymbolAddress(&p_xr, g_xr);
    cudaGetSymbolAddress(&p_r1wt, g_r1wt);
    cudaGetSymbolAddress(&p_w1t, g_w1t);
    cudaGetSymbolAddress(&p_w2t, g_w2t);
    cudaGetSymbolAddress(&p_lists, g_lists);
    cudaGetSymbolAddress(&p_counts, g_counts);
    cudaGetSymbolAddress(&p_act, g_act);
    cudaGetSymbolAddress(&p_y, g_y);

    reset_kernel<<<1, 32>>>();

    // prep: round x; transpose+round weights to [N][K]
    round_kernel<<<(NTOK * DDIM) / 1024, 256>>>(x, (float*)p_xr);
    {
        dim3 b(256);
        transpose_rna_kernel<<<dim3(HDIM / 32, DDIM / 32, 1), b>>>(r1_w, (float*)p_r1wt, DDIM, HDIM);
        transpose_rna_kernel<<<dim3(FDIM / 32, DDIM / 32, EEXP), b>>>(W1, (float*)p_w1t, DDIM, FDIM);
        transpose_rna_kernel<<<dim3(DDIM / 32, FDIM / 32, EEXP), b>>>(W2, (float*)p_w2t, FDIM, DDIM);
    }

    // Router GEMM1 (tf32 tensor): h = x @ r1_w + r1_b
    {
        dim3 grid(NTOK / TBM, 1, HDIM / TBN);
        tgemm_kernel<<<grid, 256>>>((const float*)p_xr, (const float*)p_r1wt, r1_b,
                                    (float*)p_h, nullptr, nullptr,
                                    NTOK, DDIM, HDIM, DDIM, 0, 0);
    }

    ln_gelu_kernel<<<NTOK, 256>>>(ln_g, ln_b);
    router2_kernel<<<NTOK, 128>>>(r2_w, r2_b, temp, rbias);

    // Expert GEMM1: act = rna(actfn(x[gather] @ W1[e] + b1[e]))
    {
        dim3 grid(NTOK / TBM, EEXP, FDIM / TBN);
        tgemm_kernel<<<grid, 256>>>((const float*)p_xr, (const float*)p_w1t, b1,
                                    (float*)p_act, (const int*)p_lists, (const int*)p_counts,
                                    NTOK, DDIM, FDIM, DDIM, 0, 1);
    }

    // Expert GEMM2: y = act @ W2[e] + b2[e]
    {
        dim3 grid(NTOK / TBM, EEXP, DDIM / TBN);
        tgemm_kernel<<<grid, 256>>>((const float*)p_act, (const float*)p_w2t, b2,
                                    (float*)p_y, nullptr, (const int*)p_counts,
                                    NTOK, FDIM, DDIM, FDIM,
                                    (size_t)NTOK * FDIM, 0);
    }

    combine_kernel<<<NTOK, 256>>>(out);
}